// round 1
// baseline (speedup 1.0000x reference)
#include <cuda_runtime.h>
#include <cuda_bf16.h>

// ============================================================================
// AutoInt multi-head attention, fp32 CUDA-core baseline.
// B=4096, F=40, E=64, H=4, A=64. One CTA per batch element, 256 threads.
//
// Trick: scores = X (Wq Wk^T) X^T. M_h = Wq_h Wk_h^T precomputed by a tiny
// kernel into a __device__ global (no allocs). Saves one [40,64]x[64,64] GEMM
// per head per batch (~19% of FLOPs).
//
// Per head:
//   t  = X @ M_h            [40,64]
//   v  = X @ Wv_h           [40,64]
//   P  = t @ X^T            [40,40]   (X^T staged as XST for conflict-free B reads)
//   attn = softmax(P)                 (warp-per-row, shfl reductions)
//   out_blk = attn @ v + X @ Wres[:,h*64:(h+1)*64]; relu; store
// ============================================================================

#define B_DIM 4096
#define F_DIM 40
#define E_DIM 64
#define A_DIM 64
#define H_DIM 4

// Shared-memory layout (floats)
#define XS_LD   65              // padded row stride for X  (conflict avoidance)
#define XST_LD  41              // padded row stride for X^T
#define OFF_XS   0
#define OFF_XST  (OFF_XS + F_DIM * XS_LD)            // 2600
#define OFF_WA   (OFF_XST + E_DIM * XST_LD)          // 2600+2624 = 5224
#define OFF_WB   (OFF_WA + 64 * 64)                  // +4096
#define OFF_TS   (OFF_WB + 64 * 64)                  // +4096
#define OFF_VS   (OFF_TS + F_DIM * 64)               // +2560
#define OFF_PS   (OFF_VS + F_DIM * 64)               // +2560
#define SMEM_FLOATS (OFF_PS + F_DIM * F_DIM)         // +1600 = 20136
#define SMEM_BYTES  (SMEM_FLOATS * 4)                // 80544 B

__device__ float g_M[H_DIM * E_DIM * E_DIM];   // M_h = Wq_h @ Wk_h^T

// --------------------------------------------------------------------------
// Precompute M_h. grid = H, block = 256.
// --------------------------------------------------------------------------
__global__ void precompute_M_kernel(const float* __restrict__ Wq,
                                    const float* __restrict__ Wk) {
    int h = blockIdx.x;
    __shared__ float sq[E_DIM * A_DIM];
    __shared__ float sk[E_DIM * A_DIM];
    const float* wq = Wq + h * E_DIM * A_DIM;
    const float* wk = Wk + h * E_DIM * A_DIM;
    for (int i = threadIdx.x; i < E_DIM * A_DIM; i += 256) {
        sq[i] = wq[i];
        sk[i] = wk[i];
    }
    __syncthreads();
    for (int idx = threadIdx.x; idx < E_DIM * E_DIM; idx += 256) {
        int e  = idx >> 6;
        int ep = idx & 63;
        float s = 0.f;
        #pragma unroll 8
        for (int a = 0; a < A_DIM; a++)
            s = fmaf(sq[e * A_DIM + a], sk[ep * A_DIM + a], s);
        g_M[h * E_DIM * E_DIM + idx] = s;
    }
}

// --------------------------------------------------------------------------
// Register-tiled GEMM fragment: each participating thread accumulates a
// 5-row x 2-col tile of C[40, 2*NCG]. rows f = ty + 8*i, cols c = 2*tx.
// --------------------------------------------------------------------------
__device__ __forceinline__ void gemm_acc(const float* __restrict__ A, int lda,
                                         const float* __restrict__ B, int ldb,
                                         int K, int tx, int ty,
                                         float acc[5][2]) {
    #pragma unroll 4
    for (int k = 0; k < K; k++) {
        float b0 = B[k * ldb + 2 * tx];
        float b1 = B[k * ldb + 2 * tx + 1];
        #pragma unroll
        for (int i = 0; i < 5; i++) {
            float a = A[(ty + 8 * i) * lda + k];
            acc[i][0] = fmaf(a, b0, acc[i][0]);
            acc[i][1] = fmaf(a, b1, acc[i][1]);
        }
    }
}

__device__ __forceinline__ void store_C(float* __restrict__ C, int ldc,
                                        int tx, int ty, const float acc[5][2]) {
    #pragma unroll
    for (int i = 0; i < 5; i++) {
        C[(ty + 8 * i) * ldc + 2 * tx]     = acc[i][0];
        C[(ty + 8 * i) * ldc + 2 * tx + 1] = acc[i][1];
    }
}

// --------------------------------------------------------------------------
// Main kernel. grid = B, block = 256, dynamic smem = SMEM_BYTES.
// --------------------------------------------------------------------------
__global__ void __launch_bounds__(256, 2)
attn_main_kernel(const float* __restrict__ Xg,
                 const float* __restrict__ Wv,
                 const float* __restrict__ Wres,
                 float* __restrict__ out) {
    extern __shared__ float sm[];
    float* XS  = sm + OFF_XS;
    float* XST = sm + OFF_XST;
    float* WA  = sm + OFF_WA;
    float* WB  = sm + OFF_WB;
    float* TS  = sm + OFF_TS;
    float* VS  = sm + OFF_VS;
    float* PS  = sm + OFF_PS;

    const int tid = threadIdx.x;
    const int b   = blockIdx.x;
    const float* xb = Xg + (size_t)b * F_DIM * E_DIM;

    // Load X [40,64] into XS (padded) and XST (transposed, padded)
    for (int i = tid; i < F_DIM * E_DIM / 4; i += 256) {
        float4 v = reinterpret_cast<const float4*>(xb)[i];
        int f  = i >> 4;
        int e4 = (i & 15) * 4;
        float* d = XS + f * XS_LD + e4;
        d[0] = v.x; d[1] = v.y; d[2] = v.z; d[3] = v.w;
        XST[(e4 + 0) * XST_LD + f] = v.x;
        XST[(e4 + 1) * XST_LD + f] = v.y;
        XST[(e4 + 2) * XST_LD + f] = v.z;
        XST[(e4 + 3) * XST_LD + f] = v.w;
    }

    const int tx = tid & 31;        // col group for 64-wide GEMMs
    const int ty = tid >> 5;        // row group
    const int sx = tid % 20;        // col group for 40-wide scores GEMM
    const int sy = tid / 20;

    for (int h = 0; h < H_DIM; h++) {
        __syncthreads();  // protects WA/WB/XS/XST/PS against previous stage

        // Stage M_h -> WA, Wv_h -> WB
        {
            const float4* msrc = reinterpret_cast<const float4*>(g_M + h * 4096);
            const float4* vsrc = reinterpret_cast<const float4*>(Wv + h * 4096);
            for (int i = tid; i < 1024; i += 256) {
                reinterpret_cast<float4*>(WA)[i] = msrc[i];
                reinterpret_cast<float4*>(WB)[i] = vsrc[i];
            }
        }
        __syncthreads();

        // TS = XS @ WA, VS = XS @ WB
        {
            float acc[5][2] = {};
            gemm_acc(XS, XS_LD, WA, 64, E_DIM, tx, ty, acc);
            store_C(TS, 64, tx, ty, acc);
        }
        {
            float acc[5][2] = {};
            gemm_acc(XS, XS_LD, WB, 64, E_DIM, tx, ty, acc);
            store_C(VS, 64, tx, ty, acc);
        }
        __syncthreads();

        // Restage WA = Wres[:, h*64 : h*64+64]  (WA free after TS)
        for (int i = tid; i < 1024; i += 256) {
            int e  = i >> 4;
            int c4 = i & 15;
            reinterpret_cast<float4*>(WA + e * 64)[c4] =
                *reinterpret_cast<const float4*>(Wres + e * 256 + h * 64 + c4 * 4);
        }

        // Scores: PS[40,40] = TS @ XST   (160 threads participate)
        if (tid < 160) {
            float acc[5][2] = {};
            gemm_acc(TS, 64, XST, XST_LD, E_DIM, sx, sy, acc);
            store_C(PS, 40, sx, sy, acc);
        }
        __syncthreads();

        // Softmax over rows of PS: warp w handles rows w, w+8, ..., w+32
        {
            int w    = tid >> 5;
            int lane = tid & 31;
            #pragma unroll
            for (int j = 0; j < 5; j++) {
                int r = w + 8 * j;
                float v1 = PS[r * 40 + lane];
                float v2 = (lane < 8) ? PS[r * 40 + 32 + lane] : -3.4e38f;
                float m = fmaxf(v1, v2);
                #pragma unroll
                for (int o = 16; o; o >>= 1)
                    m = fmaxf(m, __shfl_xor_sync(0xffffffffu, m, o));
                float e1 = __expf(v1 - m);
                float e2 = (lane < 8) ? __expf(v2 - m) : 0.f;
                float s = e1 + e2;
                #pragma unroll
                for (int o = 16; o; o >>= 1)
                    s += __shfl_xor_sync(0xffffffffu, s, o);
                float inv = 1.f / s;
                PS[r * 40 + lane] = e1 * inv;
                if (lane < 8) PS[r * 40 + 32 + lane] = e2 * inv;
            }
        }
        __syncthreads();

        // out_blk = attn @ VS + XS @ WresBlk ; relu ; store
        {
            float acc[5][2] = {};
            gemm_acc(PS, 40, VS, 64, F_DIM, tx, ty, acc);   // heads (K=40)
            gemm_acc(XS, XS_LD, WA, 64, E_DIM, tx, ty, acc); // residual (K=64)
            float* ob = out + (size_t)b * (F_DIM * 256) + h * 64 + 2 * tx;
            #pragma unroll
            for (int i = 0; i < 5; i++) {
                int f = ty + 8 * i;
                ob[f * 256 + 0] = fmaxf(acc[i][0], 0.f);
                ob[f * 256 + 1] = fmaxf(acc[i][1], 0.f);
            }
        }
    }
}

// --------------------------------------------------------------------------
extern "C" void kernel_launch(void* const* d_in, const int* in_sizes, int n_in,
                              void* d_out, int out_size) {
    const float* X    = (const float*)d_in[0];
    const float* Wq   = (const float*)d_in[1];
    const float* Wk   = (const float*)d_in[2];
    const float* Wv   = (const float*)d_in[3];
    const float* Wres = (const float*)d_in[4];
    float* out = (float*)d_out;

    cudaFuncSetAttribute(attn_main_kernel,
                         cudaFuncAttributeMaxDynamicSharedMemorySize, SMEM_BYTES);

    precompute_M_kernel<<<H_DIM, 256>>>(Wq, Wk);
    attn_main_kernel<<<B_DIM, 256, SMEM_BYTES>>>(X, Wv, Wres, out);
}

// round 2
// speedup vs baseline: 1.1478x; 1.1478x over previous
#include <cuda_runtime.h>
#include <cuda_bf16.h>

// ============================================================================
// AutoInt multi-head attention — fp32 with packed FFMA2 (fma.rn.f32x2).
// B=4096, F=40, E=64, H=4, A=64. One CTA per batch, 256 threads, 2 CTAs/SM.
//
// Round-2 changes vs round-1 (which was L1TEX/crossbar-bound at 90.6%):
//  * Warp mapping: warp owns 8 columns x all 40 rows (lane = rowgrp*4+colgrp)
//    -> A loads are 8-address broadcasts (1 wavefront), B loads 4-address
//    broadcasts (1 wavefront), no cross-warp B re-read blowup.
//  * All "A" matrices stored DUPLICATED ({a,a} pairs) in smem so packed
//    fma.rn.f32x2 needs zero pack instructions: LDS.128 yields two packed
//    A operands (k, k+1); B pairs load as LDS.64 directly.
//  * scores = X (Wq Wk^T) X^T with M precomputed (19% FLOP cut, unchanged).
// ============================================================================

#define B_DIM 4096
#define F_DIM 40
#define E_DIM 64
#define A_DIM 64
#define H_DIM 4

typedef unsigned long long ULL;

// ---- shared memory layout (floats) ----------------------------------------
#define XSD_LD 132   // X duplicated: [40][128] (+pad), 16B-aligned rows
#define XST_LD 44    // X^T: [64][40] (+pad)
#define TSD_LD 132   // t duplicated: [40][128]
#define VS_LD  68    // v: [40][64] (+pad)
#define PSD_LD 88    // attn duplicated: [40][80] (+pad)

#define OFF_XSD 0
#define OFF_XST (OFF_XSD + F_DIM * XSD_LD)      // 5280
#define OFF_WA  (OFF_XST + E_DIM * XST_LD)      // 8096
#define OFF_WB  (OFF_WA + 64 * 64)              // 12192
#define OFF_TSD (OFF_WB + 64 * 64)              // 16288
#define OFF_VS  (OFF_TSD + F_DIM * TSD_LD)      // 21568
#define OFF_PSD (OFF_VS + F_DIM * VS_LD)        // 24288
#define SMEM_FLOATS (OFF_PSD + F_DIM * PSD_LD)  // 27808
#define SMEM_BYTES  (SMEM_FLOATS * 4)           // 111232 B -> 2 CTAs/SM

__device__ float g_M[H_DIM * E_DIM * E_DIM];    // M_h = Wq_h @ Wk_h^T

// ---- packed f32x2 helpers ---------------------------------------------------
__device__ __forceinline__ void fma2(ULL& acc, ULL a, ULL b) {
    asm("fma.rn.f32x2 %0, %1, %2, %3;" : "=l"(acc) : "l"(a), "l"(b), "l"(acc));
}
__device__ __forceinline__ float2 unpack2(ULL v) {
    float2 r;
    asm("mov.b64 {%0, %1}, %2;" : "=f"(r.x), "=f"(r.y) : "l"(v));
    return r;
}

// ----------------------------------------------------------------------------
__global__ void precompute_M_kernel(const float* __restrict__ Wq,
                                    const float* __restrict__ Wk) {
    int h = blockIdx.x;
    __shared__ float sq[E_DIM * A_DIM];
    __shared__ float sk[E_DIM * A_DIM];
    const float* wq = Wq + h * E_DIM * A_DIM;
    const float* wk = Wk + h * E_DIM * A_DIM;
    for (int i = threadIdx.x; i < E_DIM * A_DIM; i += 256) {
        sq[i] = wq[i];
        sk[i] = wk[i];
    }
    __syncthreads();
    for (int idx = threadIdx.x; idx < E_DIM * E_DIM; idx += 256) {
        int e  = idx >> 6;
        int ep = idx & 63;
        float s = 0.f;
        #pragma unroll 8
        for (int a = 0; a < A_DIM; a++)
            s = fmaf(sq[e * A_DIM + a], sk[ep * A_DIM + a], s);
        g_M[h * E_DIM * E_DIM + idx] = s;
    }
}

// ----------------------------------------------------------------------------
__global__ void __launch_bounds__(256, 2)
attn_main_kernel(const float* __restrict__ Xg,
                 const float* __restrict__ Wv,
                 const float* __restrict__ Wres,
                 float* __restrict__ out) {
    extern __shared__ float sm[];
    float* XSD = sm + OFF_XSD;
    float* XST = sm + OFF_XST;
    float* WA  = sm + OFF_WA;
    float* WB  = sm + OFF_WB;
    float* TSD = sm + OFF_TSD;
    float* VS  = sm + OFF_VS;
    float* PSD = sm + OFF_PSD;

    const int tid  = threadIdx.x;
    const int b    = blockIdx.x;
    const int w    = tid >> 5;
    const int lane = tid & 31;
    const int rg   = lane >> 2;          // row group: rows rg, rg+8, ..., rg+32
    const int cg   = lane & 3;           // col-pair within warp
    const int p    = w * 4 + cg;         // global col-pair 0..31 -> cols 2p,2p+1

    const float* xb = Xg + (size_t)b * (F_DIM * E_DIM);

    // ---- load X into XSD (duplicated) and XST (transposed) ----
    for (int i = tid; i < F_DIM * E_DIM / 4; i += 256) {
        float4 v = reinterpret_cast<const float4*>(xb)[i];
        int f  = i >> 4;
        int e4 = (i & 15) * 4;
        float4* d = reinterpret_cast<float4*>(XSD + f * XSD_LD + 2 * e4);
        d[0] = make_float4(v.x, v.x, v.y, v.y);
        d[1] = make_float4(v.z, v.z, v.w, v.w);
        XST[(e4 + 0) * XST_LD + f] = v.x;
        XST[(e4 + 1) * XST_LD + f] = v.y;
        XST[(e4 + 2) * XST_LD + f] = v.z;
        XST[(e4 + 3) * XST_LD + f] = v.w;
    }

    for (int h = 0; h < H_DIM; h++) {
        __syncthreads();   // protect WA/WB (+ XSD/XST on first iter)

        // ---- stage WA = M_h, WB = Wv_h ----
        {
            const float4* msrc = reinterpret_cast<const float4*>(g_M + h * 4096);
            const float4* vsrc = reinterpret_cast<const float4*>(Wv + h * 4096);
            for (int i = tid; i < 1024; i += 256) {
                reinterpret_cast<float4*>(WA)[i] = msrc[i];
                reinterpret_cast<float4*>(WB)[i] = vsrc[i];
            }
        }
        __syncthreads();

        // ---- GEMM1: TS = X @ M_h, VS = X @ Wv_h (K=64, packed) ----
        {
            ULL ts[5] = {0, 0, 0, 0, 0};
            ULL vs[5] = {0, 0, 0, 0, 0};
            #pragma unroll 4
            for (int k2 = 0; k2 < 32; k2++) {
                int k = 2 * k2;
                ULL bA0 = *reinterpret_cast<const ULL*>(WA + k * 64 + 2 * p);
                ULL bA1 = *reinterpret_cast<const ULL*>(WA + k * 64 + 64 + 2 * p);
                ULL bB0 = *reinterpret_cast<const ULL*>(WB + k * 64 + 2 * p);
                ULL bB1 = *reinterpret_cast<const ULL*>(WB + k * 64 + 64 + 2 * p);
                #pragma unroll
                for (int i = 0; i < 5; i++) {
                    ulonglong2 a = *reinterpret_cast<const ulonglong2*>(
                        XSD + (rg + 8 * i) * XSD_LD + 2 * k);
                    fma2(ts[i], a.x, bA0);
                    fma2(ts[i], a.y, bA1);
                    fma2(vs[i], a.x, bB0);
                    fma2(vs[i], a.y, bB1);
                }
            }
            #pragma unroll
            for (int i = 0; i < 5; i++) {
                int r = rg + 8 * i;
                float2 t = unpack2(ts[i]);
                float2 v = unpack2(vs[i]);
                *reinterpret_cast<float4*>(TSD + r * TSD_LD + 4 * p) =
                    make_float4(t.x, t.x, t.y, t.y);           // duplicated
                *reinterpret_cast<float2*>(VS + r * VS_LD + 2 * p) =
                    make_float2(v.x, v.y);                     // scalar
            }
        }
        __syncthreads();

        // ---- PS = TS @ X^T (K=64, packed), warps 0-4; warps 5-7 stage Wres ----
        if (w < 5) {
            int q = p;                       // col-pair 0..19 -> cols 2q,2q+1
            ULL ps[5] = {0, 0, 0, 0, 0};
            #pragma unroll 4
            for (int k2 = 0; k2 < 32; k2++) {
                int k = 2 * k2;
                ULL b0 = *reinterpret_cast<const ULL*>(XST + k * XST_LD + 2 * q);
                ULL b1 = *reinterpret_cast<const ULL*>(XST + (k + 1) * XST_LD + 2 * q);
                #pragma unroll
                for (int i = 0; i < 5; i++) {
                    ulonglong2 a = *reinterpret_cast<const ulonglong2*>(
                        TSD + (rg + 8 * i) * TSD_LD + 2 * k);
                    fma2(ps[i], a.x, b0);
                    fma2(ps[i], a.y, b1);
                }
            }
            #pragma unroll
            for (int i = 0; i < 5; i++) {
                float2 s = unpack2(ps[i]);
                *reinterpret_cast<float4*>(PSD + (rg + 8 * i) * PSD_LD + 4 * q) =
                    make_float4(s.x, s.x, s.y, s.y);           // duplicated
            }
        } else {
            // stage WA <- Wres[:, h*64:(h+1)*64]   (WA free after GEMM1)
            for (int i = tid - 160; i < 1024; i += 96) {
                int e  = i >> 4;
                int c4 = i & 15;
                reinterpret_cast<float4*>(WA + e * 64)[c4] =
                    *reinterpret_cast<const float4*>(Wres + e * 256 + h * 64 + 4 * c4);
            }
        }
        __syncthreads();

        // ---- softmax over rows of PSD (duplicated layout, stride 2) ----
        {
            #pragma unroll
            for (int j = 0; j < 5; j++) {
                int r = w + 8 * j;
                float v1 = PSD[r * PSD_LD + 2 * lane];
                float v2 = (lane < 8) ? PSD[r * PSD_LD + 2 * (32 + lane)] : -3.4e38f;
                float m = fmaxf(v1, v2);
                #pragma unroll
                for (int o = 16; o; o >>= 1)
                    m = fmaxf(m, __shfl_xor_sync(0xffffffffu, m, o));
                float e1 = __expf(v1 - m);
                float e2 = (lane < 8) ? __expf(v2 - m) : 0.f;
                float s = e1 + e2;
                #pragma unroll
                for (int o = 16; o; o >>= 1)
                    s += __shfl_xor_sync(0xffffffffu, s, o);
                float inv = 1.f / s;
                float q1 = e1 * inv;
                *reinterpret_cast<float2*>(PSD + r * PSD_LD + 2 * lane) =
                    make_float2(q1, q1);
                if (lane < 8) {
                    float q2 = e2 * inv;
                    *reinterpret_cast<float2*>(PSD + r * PSD_LD + 2 * (32 + lane)) =
                        make_float2(q2, q2);
                }
            }
        }
        __syncthreads();

        // ---- out = attn @ VS (K=40) + X @ WresBlk (K=64), packed; relu; store
        {
            ULL acc[5] = {0, 0, 0, 0, 0};
            #pragma unroll 4
            for (int k2 = 0; k2 < 20; k2++) {          // attn @ VS
                int k = 2 * k2;
                ULL b0 = *reinterpret_cast<const ULL*>(VS + k * VS_LD + 2 * p);
                ULL b1 = *reinterpret_cast<const ULL*>(VS + (k + 1) * VS_LD + 2 * p);
                #pragma unroll
                for (int i = 0; i < 5; i++) {
                    ulonglong2 a = *reinterpret_cast<const ulonglong2*>(
                        PSD + (rg + 8 * i) * PSD_LD + 2 * k);
                    fma2(acc[i], a.x, b0);
                    fma2(acc[i], a.y, b1);
                }
            }
            #pragma unroll 4
            for (int k2 = 0; k2 < 32; k2++) {          // residual
                int k = 2 * k2;
                ULL b0 = *reinterpret_cast<const ULL*>(WA + k * 64 + 2 * p);
                ULL b1 = *reinterpret_cast<const ULL*>(WA + k * 64 + 64 + 2 * p);
                #pragma unroll
                for (int i = 0; i < 5; i++) {
                    ulonglong2 a = *reinterpret_cast<const ulonglong2*>(
                        XSD + (rg + 8 * i) * XSD_LD + 2 * k);
                    fma2(acc[i], a.x, b0);
                    fma2(acc[i], a.y, b1);
                }
            }
            float* ob = out + (size_t)b * (F_DIM * 256) + h * 64 + 2 * p;
            #pragma unroll
            for (int i = 0; i < 5; i++) {
                int f = rg + 8 * i;
                float2 r = unpack2(acc[i]);
                *reinterpret_cast<float2*>(ob + f * 256) =
                    make_float2(fmaxf(r.x, 0.f), fmaxf(r.y, 0.f));
            }
        }
    }
}

// ----------------------------------------------------------------------------
extern "C" void kernel_launch(void* const* d_in, const int* in_sizes, int n_in,
                              void* d_out, int out_size) {
    const float* X    = (const float*)d_in[0];
    const float* Wq   = (const float*)d_in[1];
    const float* Wk   = (const float*)d_in[2];
    const float* Wv   = (const float*)d_in[3];
    const float* Wres = (const float*)d_in[4];
    float* out = (float*)d_out;

    cudaFuncSetAttribute(attn_main_kernel,
                         cudaFuncAttributeMaxDynamicSharedMemorySize, SMEM_BYTES);

    precompute_M_kernel<<<H_DIM, 256>>>(Wq, Wk);
    attn_main_kernel<<<B_DIM, 256, SMEM_BYTES>>>(X, Wv, Wres, out);
}